// round 2
// baseline (speedup 1.0000x reference)
#include <cuda_runtime.h>

#define BB 8
#define CIN 128
#define COUT 128
#define HH 64
#define WW 64
#define KH 4
#define KW 4
#define KK 16
#define HO 61
#define WO 61

#define MT 64          // M tile (padded row of WO=61 pixels)
#define AS_LD 68       // As leading dim (floats); 68*4=272 bytes, 16B-aligned rows
#define SMEM_BYTES ((CIN * AS_LD + CIN * COUT) * 4)   // 34816 + 65536 = 100352 B

// Scratch (allocation-free: __device__ globals)
__device__ float g_inT[(size_t)BB * HH * WW * CIN];   // NHWC input, 16.8 MB
__device__ float g_w[(size_t)KK * CIN * COUT];        // Wr[k][c][o], flipped, 1 MB

// ---------------------------------------------------------------------------
// Kernel 1: NCHW -> NHWC transpose (one block per (b, y) row, smem-tiled)
// ---------------------------------------------------------------------------
__global__ void transpose_kernel(const float* __restrict__ inp) {
    __shared__ float tile[CIN][WW + 1];   // +1 pad: conflict-free transposed reads
    int by = blockIdx.x;
    int b = by / HH, y = by % HH;
    const float* src = inp + (size_t)b * CIN * HH * WW + (size_t)y * WW;
    for (int i = threadIdx.x; i < CIN * WW; i += blockDim.x) {
        int c = i / WW, x = i % WW;
        tile[c][x] = src[(size_t)c * HH * WW + x];   // coalesced in x
    }
    __syncthreads();
    float* dst = g_inT + ((size_t)b * HH + y) * WW * CIN;
    for (int i = threadIdx.x; i < CIN * WW; i += blockDim.x) {
        int x = i / CIN, c = i % CIN;
        dst[(size_t)x * CIN + c] = tile[c][x];       // coalesced in c
    }
}

// ---------------------------------------------------------------------------
// Kernel 2: weight reorder + spatial flip: Wr[k][c][o] = W[o][c][3-ki][3-kj]
// ---------------------------------------------------------------------------
__global__ void wreorg_kernel(const float* __restrict__ wgt) {
    int idx = blockIdx.x * blockDim.x + threadIdx.x;   // (k*CIN + c)*COUT + o
    if (idx >= KK * CIN * COUT) return;
    int o = idx % COUT;
    int c = (idx / COUT) % CIN;
    int k = idx / (COUT * CIN);
    int ki = k / KW, kj = k % KW;
    g_w[idx] = wgt[(((size_t)o * CIN + c) * KH + (KH - 1 - ki)) * KW + (KW - 1 - kj)];
}

// ---------------------------------------------------------------------------
// Kernel 3: fused bilinear sample + GEMM.
// One block per (oh, b). 128 threads, 8x8 register tile each.
// C[m=ow (0..60), n=cout] = sum_{k,c} sampled[m][k*128+c] * Wr[k][c][n]
// ---------------------------------------------------------------------------
__global__ void __launch_bounds__(128, 2)
main_kernel(const float* __restrict__ offset, const float* __restrict__ mask,
            const float* __restrict__ bias, float* __restrict__ out) {
    extern __shared__ float smem[];
    float* As = smem;                 // [CIN][AS_LD] : As[c][m]
    float* Bs = smem + CIN * AS_LD;   // [CIN][COUT]  : Bs[c][o]

    const int oh = blockIdx.x;
    const int b  = blockIdx.y;
    const int tid = threadIdx.x;

    // A-fill mapping: 2 threads per pixel, 64 channels each
    const int m_fill = tid >> 1;
    const int c0 = (tid & 1) * 64;

    // GEMM mapping: 8 m-groups x 16 n-groups, 8x8 per thread
    const int mg = tid >> 4, ng = tid & 15;
    const int m0 = mg * 8, n0 = ng * 8;

    float acc[8][8];
#pragma unroll
    for (int i = 0; i < 8; ++i)
#pragma unroll
        for (int j = 0; j < 8; ++j) acc[i][j] = 0.f;

    const float* inTb = g_inT + (size_t)b * HH * WW * CIN;

    for (int k = 0; k < KK; ++k) {
        // ---- load Bs: contiguous 64KB slice of Wr, coalesced float4 copy ----
        {
            const float4* wk = (const float4*)(g_w + (size_t)k * CIN * COUT);
            float4* Bs4 = (float4*)Bs;
#pragma unroll
            for (int j = 0; j < 32; ++j) Bs4[tid + j * 128] = wk[tid + j * 128];
        }

        // ---- fill As: bilinear gather from NHWC input ----
        if (m_fill < WO) {
            const int ki = k >> 2, kj = k & 3;
            const float dy = offset[(((size_t)b * 2 * KK + 2 * k) * HO + oh) * WO + m_fill];
            const float dx = offset[(((size_t)b * 2 * KK + 2 * k + 1) * HO + oh) * WO + m_fill];
            const float mk = mask[(((size_t)b * KK + k) * HO + oh) * WO + m_fill];
            const float y = dy + (float)ki + (float)oh;
            const float x = dx + (float)kj + (float)m_fill;
            const float y0f = floorf(y), x0f = floorf(x);
            const int y0 = (int)y0f, x0 = (int)x0f;
            const float wy = y - y0f, wx = x - x0f;
            float w00 = (1.f - wy) * (1.f - wx) * mk;
            float w01 = (1.f - wy) * wx * mk;
            float w10 = wy * (1.f - wx) * mk;
            float w11 = wy * wx * mk;
            const bool vy0 = (y0 >= 0) && (y0 < HH);
            const bool vy1 = (y0 + 1 >= 0) && (y0 + 1 < HH);
            const bool vx0 = (x0 >= 0) && (x0 < WW);
            const bool vx1 = (x0 + 1 >= 0) && (x0 + 1 < WW);
            if (!(vy0 && vx0)) w00 = 0.f;
            if (!(vy0 && vx1)) w01 = 0.f;
            if (!(vy1 && vx0)) w10 = 0.f;
            if (!(vy1 && vx1)) w11 = 0.f;
            const int y0c = min(max(y0, 0), HH - 1), y1c = min(max(y0 + 1, 0), HH - 1);
            const int x0c = min(max(x0, 0), WW - 1), x1c = min(max(x0 + 1, 0), WW - 1);
            const float4* p00 = (const float4*)(inTb + ((size_t)y0c * WW + x0c) * CIN + c0);
            const float4* p01 = (const float4*)(inTb + ((size_t)y0c * WW + x1c) * CIN + c0);
            const float4* p10 = (const float4*)(inTb + ((size_t)y1c * WW + x0c) * CIN + c0);
            const float4* p11 = (const float4*)(inTb + ((size_t)y1c * WW + x1c) * CIN + c0);
#pragma unroll
            for (int j = 0; j < 16; ++j) {
                const float4 a = p00[j], b4 = p01[j], c4 = p10[j], d4 = p11[j];
                const int cb = c0 + j * 4;
                As[(cb + 0) * AS_LD + m_fill] = w00 * a.x + w01 * b4.x + w10 * c4.x + w11 * d4.x;
                As[(cb + 1) * AS_LD + m_fill] = w00 * a.y + w01 * b4.y + w10 * c4.y + w11 * d4.y;
                As[(cb + 2) * AS_LD + m_fill] = w00 * a.z + w01 * b4.z + w10 * c4.z + w11 * d4.z;
                As[(cb + 3) * AS_LD + m_fill] = w00 * a.w + w01 * b4.w + w10 * c4.w + w11 * d4.w;
            }
        } else {
#pragma unroll
            for (int j = 0; j < 64; ++j)
                As[(c0 + j) * AS_LD + m_fill] = 0.f;
        }
        __syncthreads();

        // ---- GEMM: 128 c-iterations, 64 FMA per thread per iteration ----
#pragma unroll 4
        for (int ci = 0; ci < CIN; ++ci) {
            const float4 a0 = *(const float4*)&As[ci * AS_LD + m0];
            const float4 a1 = *(const float4*)&As[ci * AS_LD + m0 + 4];
            const float4 b0 = *(const float4*)&Bs[ci * COUT + n0];
            const float4 b1 = *(const float4*)&Bs[ci * COUT + n0 + 4];
            const float am[8] = {a0.x, a0.y, a0.z, a0.w, a1.x, a1.y, a1.z, a1.w};
            const float bn[8] = {b0.x, b0.y, b0.z, b0.w, b1.x, b1.y, b1.z, b1.w};
#pragma unroll
            for (int i = 0; i < 8; ++i)
#pragma unroll
                for (int j = 0; j < 8; ++j) acc[i][j] += am[i] * bn[j];
        }
        __syncthreads();
    }

    // ---- epilogue: add bias, write NCHW output ----
#pragma unroll
    for (int j = 0; j < 8; ++j) {
        const float bv = bias[n0 + j];
#pragma unroll
        for (int i = 0; i < 8; ++i) {
            const int ow = m0 + i;
            if (ow < WO)
                out[(((size_t)b * COUT + (n0 + j)) * HO + oh) * WO + ow] = acc[i][j] + bv;
        }
    }
}

// ---------------------------------------------------------------------------
extern "C" void kernel_launch(void* const* d_in, const int* in_sizes, int n_in,
                              void* d_out, int out_size) {
    const float* inp    = (const float*)d_in[0];
    const float* offset = (const float*)d_in[1];
    const float* mask   = (const float*)d_in[2];
    const float* weight = (const float*)d_in[3];
    const float* bias   = (const float*)d_in[4];
    float* out = (float*)d_out;

    cudaFuncSetAttribute(main_kernel, cudaFuncAttributeMaxDynamicSharedMemorySize,
                         SMEM_BYTES);

    transpose_kernel<<<BB * HH, 256>>>(inp);
    wreorg_kernel<<<(KK * CIN * COUT + 255) / 256, 256>>>(weight);
    main_kernel<<<dim3(HO, BB), 128, SMEM_BYTES>>>(offset, mask, bias, out);
}

// round 4
// speedup vs baseline: 3.5960x; 3.5960x over previous
#include <cuda_runtime.h>
#include <cstdint>

#define BB 8
#define CIN 128
#define COUT 128
#define HH 64
#define WW 64
#define KK 16
#define HO 61
#define WO 61
#define NPIX (HO * WO)        // 3721
#define MT 128                // M tile
#define MTILES 30             // ceil(3721/128)
#define NCHUNK 64             // K chunks of 32 (16 deform-k * 4 sub)

// ---- smem layout (bytes)
#define SM_AS    0            // 16384: A tile, fragment-packed [kstep4][matom8][lane32][reg4]
#define SM_BS    16384        // 16384: B tile, fragment-packed [kstep4][natom16][lane32][2]
#define SM_BIAS  32768        // 512
#define SMEM_TOTAL 33280

// Scratch (allocation-free: __device__ globals)
__device__ float g_inT[(size_t)BB * HH * WW * CIN];     // NHWC input, 16.8 MB
__device__ uint32_t g_wb[(size_t)NCHUNK * 4096];        // frag-packed tf32 weights, 1 MB

static __device__ __forceinline__ uint32_t f2tf32(float f) {
    uint32_t r;
    asm("cvt.rn.tf32.f32 %0, %1;" : "=r"(r) : "f"(f));
    return r;
}

static __device__ __forceinline__ void mma8(float* d, const uint32_t* a, const uint32_t* b) {
    asm volatile(
        "mma.sync.aligned.m16n8k8.row.col.f32.tf32.tf32.f32 "
        "{%0,%1,%2,%3}, {%4,%5,%6,%7}, {%8,%9}, {%0,%1,%2,%3};"
        : "+f"(d[0]), "+f"(d[1]), "+f"(d[2]), "+f"(d[3])
        : "r"(a[0]), "r"(a[1]), "r"(a[2]), "r"(a[3]), "r"(b[0]), "r"(b[1]));
}

// ---------------------------------------------------------------------------
// Kernel 1: NCHW -> NHWC transpose
// ---------------------------------------------------------------------------
__global__ void transpose_kernel(const float* __restrict__ inp) {
    __shared__ float tile[CIN][WW + 1];
    int by = blockIdx.x;
    int b = by / HH, y = by % HH;
    const float* src = inp + (size_t)b * CIN * HH * WW + (size_t)y * WW;
    for (int i = threadIdx.x; i < CIN * WW; i += blockDim.x) {
        int c = i / WW, x = i % WW;
        tile[c][x] = src[(size_t)c * HH * WW + x];
    }
    __syncthreads();
    float* dst = g_inT + ((size_t)b * HH + y) * WW * CIN;
    for (int i = threadIdx.x; i < CIN * WW; i += blockDim.x) {
        int x = i / CIN, c = i % CIN;
        dst[(size_t)x * CIN + c] = tile[c][x];
    }
}

// ---------------------------------------------------------------------------
// Kernel 2: weight flip + tf32 + pack in mma B-fragment order.
// g_wb[t][s(4)][na(16)][lane(32)][pair(2)]:
//   value = Wflip[n = na*8 + lane>>2][kglob = t*32 + s*8 + (lane&3) + pair*4]
//   Wflip[n][kglob]: c = (t&3)*32 + klocal ... full mapping below.
// ---------------------------------------------------------------------------
__global__ void wpack_kernel(const float* __restrict__ wgt) {
    int idx = blockIdx.x * blockDim.x + threadIdx.x;
    if (idx >= NCHUNK * 4096) return;
    int pair = idx & 1;
    int lane = (idx >> 1) & 31;
    int na   = (idx >> 6) & 15;
    int s    = (idx >> 10) & 3;
    int t    = idx >> 12;
    int n = na * 8 + (lane >> 2);
    int kc = s * 8 + (lane & 3) + pair * 4;      // k within 32-chunk
    int c = (t & 3) * 32 + kc;
    int dk = t >> 2;                              // deform kernel index
    int ki = dk >> 2, kj = dk & 3;
    float v = wgt[(((size_t)n * CIN + c) * 4 + (3 - ki)) * 4 + (3 - kj)];
    g_wb[idx] = f2tf32(v);
}

// ---------------------------------------------------------------------------
// Kernel 3: fused bilinear sample + tf32 mma.sync GEMM.
// Block (mtile, b): C[128 pixels][128 couts] = sum_{k=0..2047} A*B.
// 256 threads = 8 warps; warp w: mw=w&3 -> matoms {2mw,2mw+1}, nw=w>>2 -> natoms nw*8..+7
// ---------------------------------------------------------------------------
__global__ void __launch_bounds__(256, 2)
main_kernel(const float* __restrict__ offset, const float* __restrict__ mask,
            const float* __restrict__ bias, float* __restrict__ out) {
    extern __shared__ char smem[];
    float* As_f = (float*)(smem + SM_AS);
    float* Bs_f = (float*)(smem + SM_BS);
    float* bias_s = (float*)(smem + SM_BIAS);

    const int tid = threadIdx.x;
    const int mtile = blockIdx.x;
    const int b = blockIdx.y;
    const int lane = tid & 31;
    const int wid = tid >> 5;
    const int mw = wid & 3, nw = wid >> 2;

    if (tid < COUT) bias_s[tid] = bias[tid];

    // fill-thread mapping: 2 threads per pixel, 16 channels each
    const int px = tid >> 1;
    const int h = tid & 1;
    const int matom_w = px >> 4;
    const int rm = px & 15;
    const int p = mtile * MT + px;
    const bool pvalid = p < NPIX;
    const int oh = pvalid ? p / WO : 0;
    const int ow = pvalid ? p % WO : 0;

    const float* inTb = g_inT + (size_t)b * HH * WW * CIN;

    float acc[2][8][4];
#pragma unroll
    for (int i = 0; i < 2; ++i)
#pragma unroll
        for (int j = 0; j < 8; ++j)
#pragma unroll
            for (int e = 0; e < 4; ++e) acc[i][j][e] = 0.f;

    float4 wv = {0.f, 0.f, 0.f, 0.f};
    int4 bv = {0, 0, 0, 0};

    for (int t = 0; t < NCHUNK; ++t) {
        // ---- new deform-k: compute bilinear params in-register ----
        if ((t & 3) == 0) {
            const int dk = t >> 2;
            wv = make_float4(0.f, 0.f, 0.f, 0.f);
            bv = make_int4(0, 0, 0, 0);
            if (pvalid) {
                const int ki = dk >> 2, kj = dk & 3;
                size_t o_base = (((size_t)b * 2 * KK + 2 * dk) * HO + oh) * WO + ow;
                float dy = offset[o_base];
                float dx = offset[o_base + (size_t)HO * WO];
                float mk = mask[(((size_t)b * KK + dk) * HO + oh) * WO + ow];
                float y = dy + (float)(ki + oh);
                float x = dx + (float)(kj + ow);
                float y0f = floorf(y), x0f = floorf(x);
                int y0 = (int)y0f, x0 = (int)x0f;
                float wy = y - y0f, wx = x - x0f;
                float w00 = (1.f - wy) * (1.f - wx) * mk;
                float w01 = (1.f - wy) * wx * mk;
                float w10 = wy * (1.f - wx) * mk;
                float w11 = wy * wx * mk;
                bool vy0 = (y0 >= 0) && (y0 < HH);
                bool vy1 = (y0 + 1 >= 0) && (y0 + 1 < HH);
                bool vx0 = (x0 >= 0) && (x0 < WW);
                bool vx1 = (x0 + 1 >= 0) && (x0 + 1 < WW);
                wv.x = (vy0 && vx0) ? w00 : 0.f;
                wv.y = (vy0 && vx1) ? w01 : 0.f;
                wv.z = (vy1 && vx0) ? w10 : 0.f;
                wv.w = (vy1 && vx1) ? w11 : 0.f;
                int y0c = min(max(y0, 0), HH - 1), y1c = min(max(y0 + 1, 0), HH - 1);
                int x0c = min(max(x0, 0), WW - 1), x1c = min(max(x0 + 1, 0), WW - 1);
                bv.x = (y0c * WW + x0c) * CIN;
                bv.y = (y0c * WW + x1c) * CIN;
                bv.z = (y1c * WW + x0c) * CIN;
                bv.w = (y1c * WW + x1c) * CIN;
            }
        }

        // ---- fill A tile (fragment-packed) via bilinear gather ----
        {
            const int coff = (t & 3) * 32 + h * 16;
            const float4* q00 = (const float4*)(inTb + bv.x + coff);
            const float4* q01 = (const float4*)(inTb + bv.y + coff);
            const float4* q10 = (const float4*)(inTb + bv.z + coff);
            const float4* q11 = (const float4*)(inTb + bv.w + coff);
            // base word index pieces (reg = (rm>>3) + 2*((j>>2)&1))
            const int lane_a = (rm & 7) * 4;
            const int rhi = rm >> 3;
#pragma unroll
            for (int j4 = 0; j4 < 4; ++j4) {
                float4 a = q00[j4], b2 = q01[j4], c2 = q10[j4], d2 = q11[j4];
                float vs0 = wv.x * a.x + wv.y * b2.x + wv.z * c2.x + wv.w * d2.x;
                float vs1 = wv.x * a.y + wv.y * b2.y + wv.z * c2.y + wv.w * d2.y;
                float vs2 = wv.x * a.z + wv.y * b2.z + wv.z * c2.z + wv.w * d2.z;
                float vs3 = wv.x * a.w + wv.y * b2.w + wv.z * c2.w + wv.w * d2.w;
#pragma unroll
                for (int e = 0; e < 4; ++e) {
                    int j = j4 * 4 + e;                        // 0..15
                    int kstep = h * 2 + (j >> 3);              // 0..3
                    int word = ((kstep * 8 + matom_w) * 32 + lane_a + (j & 3)) * 4
                               + rhi + 2 * ((j >> 2) & 1);
                    float v = (e == 0) ? vs0 : (e == 1) ? vs1 : (e == 2) ? vs2 : vs3;
                    As_f[word] = __uint_as_float(f2tf32(v));
                }
            }
        }
        // ---- copy B tile (already fragment-packed, 16 KB) ----
        {
            const uint4* src = (const uint4*)(g_wb + (size_t)t * 4096);
            uint4* dst = (uint4*)Bs_f;
#pragma unroll
            for (int j = 0; j < 4; ++j) dst[tid + j * 256] = src[tid + j * 256];
        }
        __syncthreads();

        // ---- mma: 4 ksteps x (2 matoms x 8 natoms) ----
#pragma unroll
        for (int s = 0; s < 4; ++s) {
            uint32_t af[2][4];
#pragma unroll
            for (int ma = 0; ma < 2; ++ma) {
                uint4 v = *(const uint4*)&As_f[((s * 8 + (mw * 2 + ma)) * 32 + lane) * 4];
                af[ma][0] = v.x; af[ma][1] = v.y; af[ma][2] = v.z; af[ma][3] = v.w;
            }
            uint32_t bf[8][2];
#pragma unroll
            for (int na = 0; na < 8; ++na) {
                uint2 v = *(const uint2*)&Bs_f[((s * 16 + nw * 8 + na) * 32 + lane) * 2];
                bf[na][0] = v.x; bf[na][1] = v.y;
            }
#pragma unroll
            for (int ma = 0; ma < 2; ++ma)
#pragma unroll
                for (int na = 0; na < 8; ++na)
                    mma8(acc[ma][na], af[ma], bf[na]);
        }
        __syncthreads();
    }

    // ---- epilogue: stage through smem for coalesced NCHW writes ----
    float* Cs = (float*)(smem + SM_AS);   // 64 n x 128 m = 32 KB (As+Bs region)
    float* ob = out + (size_t)b * COUT * NPIX;
#pragma unroll 1
    for (int nhalf = 0; nhalf < 2; ++nhalf) {
        if (nw == nhalf) {
#pragma unroll
            for (int ma = 0; ma < 2; ++ma)
#pragma unroll
                for (int na = 0; na < 8; ++na)
#pragma unroll
                    for (int d = 0; d < 4; ++d) {
                        int nl = na * 8 + (lane & 3) * 2 + (d & 1);
                        int m = (mw * 2 + ma) * 16 + (lane >> 2) + 8 * (d >> 1);
                        Cs[nl * 128 + m] = acc[ma][na][d];
                    }
        }
        __syncthreads();
#pragma unroll
        for (int it = 0; it < 32; ++it) {
            int idx = tid + it * 256;
            int nl = idx >> 7, m = idx & 127;
            int pp = mtile * MT + m;
            int n = nhalf * 64 + nl;
            if (pp < NPIX)
                ob[(size_t)n * NPIX + pp] = Cs[idx] + bias_s[n];
        }
        __syncthreads();
    }
}

// ---------------------------------------------------------------------------
extern "C" void kernel_launch(void* const* d_in, const int* in_sizes, int n_in,
                              void* d_out, int out_size) {
    const float* inp    = (const float*)d_in[0];
    const float* offset = (const float*)d_in[1];
    const float* mask   = (const float*)d_in[2];
    const float* weight = (const float*)d_in[3];
    const float* bias   = (const float*)d_in[4];
    float* out = (float*)d_out;

    cudaFuncSetAttribute(main_kernel, cudaFuncAttributeMaxDynamicSharedMemorySize,
                         SMEM_TOTAL);

    transpose_kernel<<<BB * HH, 256>>>(inp);
    wpack_kernel<<<(NCHUNK * 4096 + 255) / 256, 256>>>(weight);
    main_kernel<<<dim3(MTILES, BB), 256, SMEM_TOTAL>>>(offset, mask, bias, out);
}

// round 6
// speedup vs baseline: 4.5381x; 1.2620x over previous
#include <cuda_runtime.h>
#include <cstdint>

#define BB 8
#define CIN 128
#define COUT 128
#define HH 64
#define WW 64
#define KK 16
#define HO 61
#define WO 61
#define NPIX (HO * WO)        // 3721
#define MT 128                // M tile
#define MTILES 30             // ceil(3721/128)
#define NCHUNK 64             // K chunks of 32 (16 deform-k * 4 sub)

#define SLD 136               // As row stride (floats): bank-bijective (8k+m)
#define AS_BUF (32 * SLD)     // floats per A buffer

// ---- smem layout (bytes)
#define SM_AS    0                        // 2 x 17408 = 34816
#define SM_BS    34816                    // 2 x 16384 = 32768
#define SM_BIAS  (34816 + 32768)          // 512
#define SMEM_TOTAL (34816 + 32768 + 512)  // 68096

// Scratch (allocation-free: __device__ globals)
__device__ float g_inT[(size_t)BB * HH * WW * CIN];     // NHWC input, 16.8 MB
__device__ uint32_t g_wb[(size_t)NCHUNK * 4096];        // frag-packed tf32 weights, 1 MB

static __device__ __forceinline__ uint32_t f2tf32(float f) {
    uint32_t r;
    asm("cvt.rn.tf32.f32 %0, %1;" : "=r"(r) : "f"(f));
    return r;
}
static __device__ __forceinline__ void mma8(float* d, const uint32_t* a, const uint32_t* b) {
    asm volatile(
        "mma.sync.aligned.m16n8k8.row.col.f32.tf32.tf32.f32 "
        "{%0,%1,%2,%3}, {%4,%5,%6,%7}, {%8,%9}, {%0,%1,%2,%3};"
        : "+f"(d[0]), "+f"(d[1]), "+f"(d[2]), "+f"(d[3])
        : "r"(a[0]), "r"(a[1]), "r"(a[2]), "r"(a[3]), "r"(b[0]), "r"(b[1]));
}
static __device__ __forceinline__ void cp16(uint32_t dst, const void* src) {
    asm volatile("cp.async.cg.shared.global [%0], [%1], 16;" :: "r"(dst), "l"(src));
}
static __device__ __forceinline__ void cp_commit() {
    asm volatile("cp.async.commit_group;" ::: "memory");
}
static __device__ __forceinline__ void cp_wait0() {
    asm volatile("cp.async.wait_group 0;" ::: "memory");
}

// ---------------------------------------------------------------------------
// Kernel 1: NCHW -> NHWC transpose
// ---------------------------------------------------------------------------
__global__ void transpose_kernel(const float* __restrict__ inp) {
    __shared__ float tile[CIN][WW + 1];
    int by = blockIdx.x;
    int b = by / HH, y = by % HH;
    const float* src = inp + (size_t)b * CIN * HH * WW + (size_t)y * WW;
    for (int i = threadIdx.x; i < CIN * WW; i += blockDim.x) {
        int c = i / WW, x = i % WW;
        tile[c][x] = src[(size_t)c * HH * WW + x];
    }
    __syncthreads();
    float* dst = g_inT + ((size_t)b * HH + y) * WW * CIN;
    for (int i = threadIdx.x; i < CIN * WW; i += blockDim.x) {
        int x = i / CIN, c = i % CIN;
        dst[(size_t)x * CIN + c] = tile[c][x];
    }
}

// ---------------------------------------------------------------------------
// Kernel 2: weight flip + tf32 + pack in mma B-fragment order (same as R4).
// ---------------------------------------------------------------------------
__global__ void wpack_kernel(const float* __restrict__ wgt) {
    int idx = blockIdx.x * blockDim.x + threadIdx.x;
    if (idx >= NCHUNK * 4096) return;
    int pair = idx & 1;
    int lane = (idx >> 1) & 31;
    int na   = (idx >> 6) & 15;
    int s    = (idx >> 10) & 3;
    int t    = idx >> 12;
    int n = na * 8 + (lane >> 2);
    int kc = s * 8 + (lane & 3) + pair * 4;
    int c = (t & 3) * 32 + kc;
    int dk = t >> 2;
    int ki = dk >> 2, kj = dk & 3;
    float v = wgt[(((size_t)n * CIN + c) * 4 + (3 - ki)) * 4 + (3 - kj)];
    g_wb[idx] = f2tf32(v);
}

// ---------------------------------------------------------------------------
// Kernel 3: fused bilinear sample + tf32 mma GEMM, double-buffered pipeline.
// ---------------------------------------------------------------------------
__global__ void __launch_bounds__(256, 2)
main_kernel(const float* __restrict__ offset, const float* __restrict__ mask,
            const float* __restrict__ bias, float* __restrict__ out) {
    extern __shared__ char smem[];
    float* As = (float*)(smem + SM_AS);       // [2][32][SLD]
    float* Bs = (float*)(smem + SM_BS);       // [2][4096]
    float* bias_s = (float*)(smem + SM_BIAS);

    const int tid = threadIdx.x;
    const int mtile = blockIdx.x;
    const int b = blockIdx.y;
    const int lane = tid & 31;
    const int wid = tid >> 5;
    const int mw = wid & 3, nw = wid >> 2;

    if (tid < COUT) bias_s[tid] = bias[tid];

    // fill-thread mapping: 2 threads per pixel, 16 channels each
    const int px = tid >> 1;
    const int h = tid & 1;
    const int p = mtile * MT + px;
    const bool pvalid = p < NPIX;
    const int oh = pvalid ? p / WO : 0;
    const int ow = pvalid ? p % WO : 0;
    const float* inTb = g_inT + (size_t)b * HH * WW * CIN;

    float acc[2][8][4];
#pragma unroll
    for (int i = 0; i < 2; ++i)
#pragma unroll
        for (int j = 0; j < 8; ++j)
#pragma unroll
            for (int e = 0; e < 4; ++e) acc[i][j][e] = 0.f;

    float4 wv = {0.f, 0.f, 0.f, 0.f};
    int4 bv = {0, 0, 0, 0};
    float pdy = 0.f, pdx = 0.f, pmk = 0.f;

    auto calc_params = [&](int dk, float dy, float dx, float mk) {
        wv = make_float4(0.f, 0.f, 0.f, 0.f);
        bv = make_int4(0, 0, 0, 0);
        if (pvalid) {
            int ki = dk >> 2, kj = dk & 3;
            float y = dy + (float)(ki + oh);
            float x = dx + (float)(kj + ow);
            float y0f = floorf(y), x0f = floorf(x);
            int y0 = (int)y0f, x0 = (int)x0f;
            float wy = y - y0f, wx = x - x0f;
            float w00 = (1.f - wy) * (1.f - wx) * mk;
            float w01 = (1.f - wy) * wx * mk;
            float w10 = wy * (1.f - wx) * mk;
            float w11 = wy * wx * mk;
            bool vy0 = (y0 >= 0) && (y0 < HH);
            bool vy1 = (y0 + 1 >= 0) && (y0 + 1 < HH);
            bool vx0 = (x0 >= 0) && (x0 < WW);
            bool vx1 = (x0 + 1 >= 0) && (x0 + 1 < WW);
            wv.x = (vy0 && vx0) ? w00 : 0.f;
            wv.y = (vy0 && vx1) ? w01 : 0.f;
            wv.z = (vy1 && vx0) ? w10 : 0.f;
            wv.w = (vy1 && vx1) ? w11 : 0.f;
            int y0c = min(max(y0, 0), HH - 1), y1c = min(max(y0 + 1, 0), HH - 1);
            int x0c = min(max(x0, 0), WW - 1), x1c = min(max(x0 + 1, 0), WW - 1);
            bv.x = (y0c * WW + x0c) * CIN;
            bv.y = (y0c * WW + x1c) * CIN;
            bv.z = (y1c * WW + x0c) * CIN;
            bv.w = (y1c * WW + x1c) * CIN;
        }
    };
    auto prefetch_om = [&](int dk) {
        if (pvalid && dk < KK) {
            size_t ob = (((size_t)b * 2 * KK + 2 * dk) * HO + oh) * WO + ow;
            pdy = offset[ob];
            pdx = offset[ob + (size_t)HO * WO];
            pmk = mask[(((size_t)b * KK + dk) * HO + oh) * WO + ow];
        }
    };

    // ---- prologue: params dk0, prefetch dk1, fill chunk 0 into buffer 0 ----
    {
        float dy0 = 0.f, dx0 = 0.f, mk0 = 0.f;
        if (pvalid) {
            size_t ob = (((size_t)b * 2 * KK) * HO + oh) * WO + ow;
            dy0 = offset[ob];
            dx0 = offset[ob + (size_t)HO * WO];
            mk0 = mask[(((size_t)b * KK) * HO + oh) * WO + ow];
        }
        calc_params(0, dy0, dx0, mk0);
        prefetch_om(1);

        // B chunk 0 via cp.async
        {
            const float4* src = (const float4*)g_wb;
            uint32_t d0 = (uint32_t)__cvta_generic_to_shared(Bs);
#pragma unroll
            for (int j = 0; j < 4; ++j)
                cp16(d0 + (uint32_t)(tid + j * 256) * 16, src + tid + j * 256);
            cp_commit();
        }
        // A chunk 0 (blocking fill)
        const int coff = h * 16;   // chunk 0 -> (t&3)==0
        const float4* q00 = (const float4*)(inTb + bv.x + coff);
        const float4* q01 = (const float4*)(inTb + bv.y + coff);
        const float4* q10 = (const float4*)(inTb + bv.z + coff);
        const float4* q11 = (const float4*)(inTb + bv.w + coff);
#pragma unroll
        for (int g4 = 0; g4 < 4; ++g4) {
            float4 a = q00[g4], b2 = q01[g4], c2 = q10[g4], d2 = q11[g4];
            float vs[4];
            vs[0] = wv.x * a.x + wv.y * b2.x + wv.z * c2.x + wv.w * d2.x;
            vs[1] = wv.x * a.y + wv.y * b2.y + wv.z * c2.y + wv.w * d2.y;
            vs[2] = wv.x * a.z + wv.y * b2.z + wv.z * c2.z + wv.w * d2.z;
            vs[3] = wv.x * a.w + wv.y * b2.w + wv.z * c2.w + wv.w * d2.w;
#pragma unroll
            for (int e = 0; e < 4; ++e)
                As[(h * 16 + g4 * 4 + e) * SLD + px] = __uint_as_float(f2tf32(vs[e]));
        }
        cp_wait0();
        __syncthreads();
    }

    // ---- main loop ----
    for (int t = 0; t < NCHUNK; ++t) {
        const int cur = t & 1;
        const float* Ac = As + cur * AS_BUF;
        const float* Bc = Bs + cur * 4096;
        float* An = As + (cur ^ 1) * AS_BUF;
        const bool hn = (t < NCHUNK - 1);

        if (hn) {
            if (((t + 1) & 3) == 0) {
                int dkn = (t + 1) >> 2;
                calc_params(dkn, pdy, pdx, pmk);
                prefetch_om(dkn + 1);
            }
            // B chunk t+1 via cp.async into the other buffer
            const float4* src = (const float4*)(g_wb + (size_t)(t + 1) * 4096);
            uint32_t d0 = (uint32_t)__cvta_generic_to_shared(Bs + (cur ^ 1) * 4096);
#pragma unroll
            for (int j = 0; j < 4; ++j)
                cp16(d0 + (uint32_t)(tid + j * 256) * 16, src + tid + j * 256);
            cp_commit();
        }

        const int coff = ((t + 1) & 3) * 32 + h * 16;
        const float4* q00 = (const float4*)(inTb + bv.x + coff);
        const float4* q01 = (const float4*)(inTb + bv.y + coff);
        const float4* q10 = (const float4*)(inTb + bv.z + coff);
        const float4* q11 = (const float4*)(inTb + bv.w + coff);

        float4 ga, gb, gc, gd;
        if (hn) { ga = q00[0]; gb = q01[0]; gc = q10[0]; gd = q11[0]; }

        const uint32_t* Acu = (const uint32_t*)Ac;
        const uint32_t* Bcu = (const uint32_t*)Bc;

#pragma unroll
        for (int s = 0; s < 4; ++s) {
            // load A fragments (conflict-free LDS.32)
            uint32_t af[2][4];
            {
                const int k0 = s * 8 + (lane & 3);
                const int mbase = mw * 32 + (lane >> 2);
#pragma unroll
                for (int ma = 0; ma < 2; ++ma) {
                    const int m = mbase + ma * 16;
                    af[ma][0] = Acu[k0 * SLD + m];
                    af[ma][1] = Acu[k0 * SLD + m + 8];
                    af[ma][2] = Acu[(k0 + 4) * SLD + m];
                    af[ma][3] = Acu[(k0 + 4) * SLD + m + 8];
                }
            }
            // load B fragments
            uint32_t bf[8][2];
#pragma unroll
            for (int na = 0; na < 8; ++na) {
                uint2 v = *(const uint2*)&Bcu[((s * 16 + nw * 8 + na) * 32 + lane) * 2];
                bf[na][0] = v.x; bf[na][1] = v.y;
            }
            // MMA
#pragma unroll
            for (int ma = 0; ma < 2; ++ma)
#pragma unroll
                for (int na = 0; na < 8; ++na)
                    mma8(acc[ma][na], af[ma], bf[na]);

            // consume gather group s -> store into next A buffer, issue group s+1
            if (hn) {
                float vs[4];
                vs[0] = wv.x * ga.x + wv.y * gb.x + wv.z * gc.x + wv.w * gd.x;
                vs[1] = wv.x * ga.y + wv.y * gb.y + wv.z * gc.y + wv.w * gd.y;
                vs[2] = wv.x * ga.z + wv.y * gb.z + wv.z * gc.z + wv.w * gd.z;
                vs[3] = wv.x * ga.w + wv.y * gb.w + wv.z * gc.w + wv.w * gd.w;
#pragma unroll
                for (int e = 0; e < 4; ++e)
                    An[(h * 16 + s * 4 + e) * SLD + px] = __uint_as_float(f2tf32(vs[e]));
                if (s < 3) {
                    ga = q00[s + 1]; gb = q01[s + 1]; gc = q10[s + 1]; gd = q11[s + 1];
                }
            }
        }
        cp_wait0();
        __syncthreads();
    }

    // ---- epilogue: stage through smem for coalesced NCHW writes ----
    float* Cs = (float*)smem;   // 64 n x 128 m = 32 KB
    float* ob = out + (size_t)b * COUT * NPIX;
#pragma unroll 1
    for (int nhalf = 0; nhalf < 2; ++nhalf) {
        if (nw == nhalf) {
#pragma unroll
            for (int ma = 0; ma < 2; ++ma)
#pragma unroll
                for (int na = 0; na < 8; ++na)
#pragma unroll
                    for (int d = 0; d < 4; ++d) {
                        int nl = na * 8 + (lane & 3) * 2 + (d & 1);
                        int m = (mw * 2 + ma) * 16 + (lane >> 2) + 8 * (d >> 1);
                        Cs[nl * 128 + m] = acc[ma][na][d];
                    }
        }
        __syncthreads();
#pragma unroll
        for (int it = 0; it < 32; ++it) {
            int idx = tid + it * 256;
            int nl = idx >> 7, m = idx & 127;
            int pp = mtile * MT + m;
            int n = nhalf * 64 + nl;
            if (pp < NPIX)
                ob[(size_t)n * NPIX + pp] = Cs[idx] + bias_s[n];
        }
        __syncthreads();
    }
}

// ---------------------------------------------------------------------------
extern "C" void kernel_launch(void* const* d_in, const int* in_sizes, int n_in,
                              void* d_out, int out_size) {
    const float* inp    = (const float*)d_in[0];
    const float* offset = (const float*)d_in[1];
    const float* mask   = (const float*)d_in[2];
    const float* weight = (const float*)d_in[3];
    const float* bias   = (const float*)d_in[4];
    float* out = (float*)d_out;

    cudaFuncSetAttribute(main_kernel, cudaFuncAttributeMaxDynamicSharedMemorySize,
                         SMEM_TOTAL);

    transpose_kernel<<<BB * HH, 256>>>(inp);
    wpack_kernel<<<(NCHUNK * 4096 + 255) / 256, 256>>>(weight);
    main_kernel<<<dim3(MTILES, BB), 256, SMEM_TOTAL>>>(offset, mask, bias, out);
}